// round 16
// baseline (speedup 1.0000x reference)
#include <cuda_runtime.h>
#include <cuda_fp16.h>
#include <cstdint>

#define S_LEN 2048
#define V_DIM 1024
#define NH    16
#define HD    64
#define QKV_LD 3072
#define SCALE 0.125f

// ---------------- scratch (__device__ globals; no allocation allowed) ------
__device__ __align__(256) __half g_xh[S_LEN * V_DIM],  g_xl[S_LEN * V_DIM];
__device__ __align__(256) __half g_wqh[QKV_LD * V_DIM];
__device__ __align__(256) __half g_rh[S_LEN * V_DIM],  g_rl[S_LEN * V_DIM];
__device__ __align__(256) __half g_wph[V_DIM * V_DIM];
__device__ __align__(256) __half g_ah[S_LEN * V_DIM],  g_al[S_LEN * V_DIM];
__device__ __align__(256) __half g_woh[V_DIM * V_DIM];

// per-head fp16 tensors for flash: layout [H][S][64]
#define HSD (NH * S_LEN * HD)
__device__ __align__(256) __half g_quh[HSD], g_qul[HSD];   // q + u (hi/lo)
__device__ __align__(256) __half g_qvh[HSD], g_qvl[HSD];   // q + v (hi/lo)
__device__ __align__(256) __half g_kh[HSD];                // k (hi only)
__device__ __align__(256) __half g_vh[HSD];                // v (hi only)
__device__ __align__(256) __half g_rph[HSD];               // pos (hi only)

// ---------------- helpers ---------------------------------------------------
__device__ __forceinline__ uint32_t s2u(const void* p) {
    uint32_t a;
    asm("{ .reg .u64 t; cvta.to.shared.u64 t, %1; cvt.u32.u64 %0, t; }"
        : "=r"(a) : "l"(p));
    return a;
}
__device__ __forceinline__ void ldm4(uint32_t* f, uint32_t addr) {
    asm volatile("ldmatrix.sync.aligned.m8n8.x4.shared.b16 {%0,%1,%2,%3}, [%4];"
                 : "=r"(f[0]), "=r"(f[1]), "=r"(f[2]), "=r"(f[3]) : "r"(addr));
}
__device__ __forceinline__ void ldm4t(uint32_t* f, uint32_t addr) {
    asm volatile("ldmatrix.sync.aligned.m8n8.x4.trans.shared.b16 {%0,%1,%2,%3}, [%4];"
                 : "=r"(f[0]), "=r"(f[1]), "=r"(f[2]), "=r"(f[3]) : "r"(addr));
}
__device__ __forceinline__ void mma_f16(float* d, const uint32_t* a,
                                        const uint32_t* b) {
    asm volatile(
        "mma.sync.aligned.m16n8k16.row.col.f32.f16.f16.f32 "
        "{%0,%1,%2,%3}, {%4,%5,%6,%7}, {%8,%9}, {%0,%1,%2,%3};"
        : "+f"(d[0]), "+f"(d[1]), "+f"(d[2]), "+f"(d[3])
        : "r"(a[0]), "r"(a[1]), "r"(a[2]), "r"(a[3]), "r"(b[0]), "r"(b[1]));
}
__device__ __forceinline__ void ldsA(uint32_t* f, uint32_t tile, int m0, int k0,
                                     int lane) {
    int r = lane & 7, g = lane >> 3;
    int row = m0 + r + (g & 1) * 8;
    int kch = (k0 >> 3) + (g >> 1);
    ldm4(f, tile + row * 128 + (((kch ^ (row & 7)) & 7) << 4));
}
__device__ __forceinline__ void ldsB(uint32_t* f, uint32_t tile, int n0, int k0,
                                     int lane) {
    int r = lane & 7, g = lane >> 3;
    int row = n0 + r + (g >> 1) * 8;
    int kch = (k0 >> 3) + (g & 1);
    ldm4(f, tile + row * 128 + (((kch ^ (row & 7)) & 7) << 4));
}
__device__ __forceinline__ void ldsBT(uint32_t* f, uint32_t tile, int n0, int k0,
                                      int lane) {
    int r = lane & 7, g = lane >> 3;
    int row = k0 + r + (g & 1) * 8;
    int bch = (n0 + (g >> 1) * 8) >> 3;
    ldm4t(f, tile + row * 128 + (((bch ^ (row & 7)) & 7) << 4));
}
__device__ __forceinline__ uint32_t pack2h(float a, float b) {
    __half2 p = __floats2half2_rn(a, b);
    return *(uint32_t*)&p;
}
__device__ __forceinline__ void split2h(float a, float b, uint32_t& hi,
                                        uint32_t& lo) {
    __half ah = __float2half_rn(a), bh = __float2half_rn(b);
    __half al = __float2half_rn(a - __half2float(ah));
    __half bl = __float2half_rn(b - __half2float(bh));
    hi = (uint32_t)*(uint16_t*)&ah | ((uint32_t)*(uint16_t*)&bh << 16);
    lo = (uint32_t)*(uint16_t*)&al | ((uint32_t)*(uint16_t*)&bl << 16);
}
#define CP16(dst, src)                                                         \
    asm volatile("cp.async.cg.shared.global [%0], [%1], 16;"                   \
                 :: "r"(dst), "l"(src) : "memory")

// ---------------- fused input split: x | Wqkv | rel | Wpos | Wout ----------
__global__ __launch_bounds__(256) void split_all(
    const float4* __restrict__ x, const float4* __restrict__ wq,
    const float4* __restrict__ rel, const float4* __restrict__ wp,
    const float4* __restrict__ wo)
{
    int i = blockIdx.x * 256 + threadIdx.x;
    const float4* src; uint32_t* H; uint32_t* L; int li; bool wl;
    if (i < 524288)       { src = x;   H = (uint32_t*)g_xh;  L = (uint32_t*)g_xl; li = i; wl = true; }
    else if (i < 1310720) { src = wq;  H = (uint32_t*)g_wqh; L = nullptr; li = i - 524288;  wl = false; }
    else if (i < 1835008) { src = rel; H = (uint32_t*)g_rh;  L = (uint32_t*)g_rl; li = i - 1310720; wl = true; }
    else if (i < 2097152) { src = wp;  H = (uint32_t*)g_wph; L = nullptr; li = i - 1835008; wl = false; }
    else                  { src = wo;  H = (uint32_t*)g_woh; L = nullptr; li = i - 2097152; wl = false; }
    float4 v = src[li];
    uint32_t h0, l0, h1, l1;
    split2h(v.x, v.y, h0, l0);
    split2h(v.z, v.w, h1, l1);
    H[2 * li] = h0; H[2 * li + 1] = h1;
    if (wl) { L[2 * li] = l0; L[2 * li + 1] = l1; }
}

// ---------------------------------------------------------------------------
// C[M,N] = A[M,K] * B[N,K]^T  via mma.sync fp16 x2 (A hi+lo, B hi).
// CTA 128x256, 256 threads / 8 warps, warp tile 64x64 (2x4 warp grid).
// 3-stage cp.async pipeline (64 KB/stage).
// MODE 0: fp32 C.
// MODE 3: merged projections — blockIdx.x<12: qkv; else: pos. K=1024 both.
// ---------------------------------------------------------------------------
#define GSTAGE 65536
#define GEMM_SMEM (3 * GSTAGE + 1024)

template<int MODE>
__global__ __launch_bounds__(256, 1) void gemm_f16x2(
    const __half* __restrict__ Ah, const __half* __restrict__ Al,
    const __half* __restrict__ Bh,
    const __half* __restrict__ Ah2, const __half* __restrict__ Al2,
    const __half* __restrict__ Bh2,
    float* __restrict__ C, const float* __restrict__ u_vec,
    const float* __restrict__ v_vec, int M, int N, int K)
{
    extern __shared__ char smem[];
    uint32_t tiles = (s2u(smem) + 1023u) & ~1023u;
    const int tid = threadIdx.x;
    const int lane = tid & 31, wid = tid >> 5;
    const int wm = wid & 1, wn = wid >> 1;        // 2x4 warp grid, 64x64 tile
    const int bm = blockIdx.y * 128;

    bool seg2 = false;
    int bn;
    const __half *pA, *pL, *pB;
    if (MODE == 3 && blockIdx.x >= 12) {
        seg2 = true;
        bn = (blockIdx.x - 12) * 256;
        pA = Ah2; pL = Al2; pB = Bh2;
    } else {
        bn = blockIdx.x * 256;
        pA = Ah; pL = Al; pB = Bh;
    }

    // 16 cp.async slots per thread per stage:
    // Ah 16K (rows 0..127) | Al 16K | B 32K (rows 0..255)
    const __half* gsrc[16];
    uint32_t sdst[16];
#pragma unroll
    for (int u = 0; u < 16; u++) {
        int idx = u * 256 + tid;                  // 0..4095
        if (idx < 2048) {
            int tile = idx >> 10;                 // 0=Ah, 1=Al
            int row = (idx >> 3) & 127, cc = idx & 7;
            gsrc[u] = (tile ? pL : pA) + (size_t)(bm + row) * K + cc * 8;
            sdst[u] = tiles + (uint32_t)tile * 16384u + row * 128u
                    + (uint32_t)((cc ^ (row & 7)) << 4);
        } else {
            int idx2 = idx - 2048;
            int row = idx2 >> 3, cc = idx2 & 7;   // row 0..255
            gsrc[u] = pB + (size_t)(bn + row) * K + cc * 8;
            sdst[u] = tiles + 32768u + (uint32_t)row * 128u
                    + (uint32_t)((cc ^ (row & 7)) << 4);
        }
    }
    const int NC = K >> 6;

    float acc[4][8][4];
#pragma unroll
    for (int mi = 0; mi < 4; mi++)
#pragma unroll
        for (int ni = 0; ni < 8; ni++)
#pragma unroll
            for (int q = 0; q < 4; q++) acc[mi][ni][q] = 0.f;

    // prologue: stages 0,1 as separate groups
#pragma unroll
    for (int s = 0; s < 2; s++) {
        uint32_t so = (uint32_t)s * GSTAGE;
        int ke = s << 6;
#pragma unroll
        for (int u = 0; u < 16; u++) CP16(sdst[u] + so, gsrc[u] + ke);
        asm volatile("cp.async.commit_group;" ::: "memory");
    }

    for (int c = 0; c < NC; c++) {
        if (c + 1 < NC) asm volatile("cp.async.wait_group 1;" ::: "memory");
        else            asm volatile("cp.async.wait_group 0;" ::: "memory");
        __syncthreads();   // stage c ready; all warps done with stage c-1
        if (c + 2 < NC) {
            uint32_t so = (uint32_t)((c + 2) % 3) * GSTAGE;
            int ke = (c + 2) << 6;
#pragma unroll
            for (int u = 0; u < 16; u++) CP16(sdst[u] + so, gsrc[u] + ke);
            asm volatile("cp.async.commit_group;" ::: "memory");
        }

        uint32_t st = (uint32_t)(c % 3) * GSTAGE;
        uint32_t tAh = tiles + st, tAl = tAh + 16384u, tBh = tAl + 16384u;
#pragma unroll
        for (int ks = 0; ks < 4; ks++) {
            int k0 = ks * 16;
            uint32_t ah[16], al[16], bb[16];
#pragma unroll
            for (int mi = 0; mi < 4; mi++)
                ldsA(&ah[mi * 4], tAh, wm * 64 + mi * 16, k0, lane);
#pragma unroll
            for (int nb = 0; nb < 4; nb++)
                ldsB(&bb[nb * 4], tBh, wn * 64 + nb * 16, k0, lane);
#pragma unroll
            for (int mi = 0; mi < 4; mi++)
#pragma unroll
                for (int ni = 0; ni < 8; ni++)
                    mma_f16(acc[mi][ni], &ah[mi * 4], &bb[ni * 2]);
#pragma unroll
            for (int mi = 0; mi < 4; mi++)
                ldsA(&al[mi * 4], tAl, wm * 64 + mi * 16, k0, lane);
#pragma unroll
            for (int mi = 0; mi < 4; mi++)
#pragma unroll
                for (int ni = 0; ni < 8; ni++)
                    mma_f16(acc[mi][ni], &al[mi * 4], &bb[ni * 2]);
        }
    }

    const int r0 = lane >> 2, c0 = (lane & 3) * 2;
#pragma unroll
    for (int mi = 0; mi < 4; mi++) {
        int gm = bm + wm * 64 + mi * 16;
#pragma unroll
        for (int ni = 0; ni < 8; ni++) {
            int gn = bn + wn * 64 + ni * 8 + c0;
            if (MODE == 0) {
                float* p0 = C + (size_t)(gm + r0) * N + gn;
                float* p1 = C + (size_t)(gm + r0 + 8) * N + gn;
                *(float2*)p0 = make_float2(acc[mi][ni][0], acc[mi][ni][1]);
                *(float2*)p1 = make_float2(acc[mi][ni][2], acc[mi][ni][3]);
            } else if (seg2) {
                int hd_ = gn & 1023;
                size_t w0 = (((size_t)(hd_ >> 6) * S_LEN + gm + r0) * HD
                             + (hd_ & 63)) >> 1;
                size_t w1 = w0 + 256;           // +8 rows
                ((uint32_t*)g_rph)[w0] = pack2h(acc[mi][ni][0], acc[mi][ni][1]);
                ((uint32_t*)g_rph)[w1] = pack2h(acc[mi][ni][2], acc[mi][ni][3]);
            } else {
                int sec = gn >> 10;
                int hd_ = gn & 1023;
                size_t w0 = (((size_t)(hd_ >> 6) * S_LEN + gm + r0) * HD
                             + (hd_ & 63)) >> 1;
                size_t w1 = w0 + 256;
                uint32_t hh, ll;
                if (sec == 0) {
                    float2 uu = *(const float2*)&u_vec[hd_];
                    float2 vv = *(const float2*)&v_vec[hd_];
                    split2h(acc[mi][ni][0] + uu.x, acc[mi][ni][1] + uu.y, hh, ll);
                    ((uint32_t*)g_quh)[w0] = hh; ((uint32_t*)g_qul)[w0] = ll;
                    split2h(acc[mi][ni][2] + uu.x, acc[mi][ni][3] + uu.y, hh, ll);
                    ((uint32_t*)g_quh)[w1] = hh; ((uint32_t*)g_qul)[w1] = ll;
                    split2h(acc[mi][ni][0] + vv.x, acc[mi][ni][1] + vv.y, hh, ll);
                    ((uint32_t*)g_qvh)[w0] = hh; ((uint32_t*)g_qvl)[w0] = ll;
                    split2h(acc[mi][ni][2] + vv.x, acc[mi][ni][3] + vv.y, hh, ll);
                    ((uint32_t*)g_qvh)[w1] = hh; ((uint32_t*)g_qvl)[w1] = ll;
                } else if (sec == 1) {
                    ((uint32_t*)g_kh)[w0] = pack2h(acc[mi][ni][0], acc[mi][ni][1]);
                    ((uint32_t*)g_kh)[w1] = pack2h(acc[mi][ni][2], acc[mi][ni][3]);
                } else {
                    ((uint32_t*)g_vh)[w0] = pack2h(acc[mi][ni][0], acc[mi][ni][1]);
                    ((uint32_t*)g_vh)[w1] = pack2h(acc[mi][ni][2], acc[mi][ni][3]);
                }
            }
        }
    }
}

// ---------------------------------------------------------------------------
// Flash-attention, Transformer-XL shift — fp16 x2, 64-row CTAs, 2 CTA/SM.
// Grid (NH, 32). CTA = 64 i-rows; 4 warps; warp owns 16 rows x 64 j x 64 d.
// smem 115200 B. One __syncthreads per j-iter.   (unchanged from R13)
// ---------------------------------------------------------------------------
#define oKV 32768           /* stage*16384: Kh @0, Vh @8192 */
#define oR  65536           /* Rh 256-row ring (hi only)    */
#define oS  98304           /* fp32 [64][66] warp-private strips */
#define FL_SMEM 115200

__global__ __launch_bounds__(128) void flash_xl_mma()
{
    extern __shared__ char fsm[];
    const uint32_t base = s2u(fsm);
    float* sS = (float*)(fsm + oS);

    const int h   = blockIdx.x;
    const int i0  = 64 * (int)(gridDim.y - 1 - blockIdx.y);   // heavy first
    const int tid = threadIdx.x;
    const int lane = tid & 31, wid = tid >> 5;
    const int m0 = wid * 16;
    const int fr = lane >> 2, fc = (lane & 3) * 2;
    const int il0 = m0 + fr, il1 = il0 + 8;

    const size_t hb = (size_t)h * (S_LEN * HD);
    const __half* pQUh = g_quh + hb + (size_t)i0 * HD;
    const __half* pQUl = g_qul + hb + (size_t)i0 * HD;
    const __half* pQVh = g_qvh + hb + (size_t)i0 * HD;
    const __half* pQVl = g_qvl + hb + (size_t)i0 * HD;
    const __half* pKh  = g_kh  + hb;
    const __half* pVh  = g_vh  + hb;
    const __half* pRh  = g_rph + hb;

    auto fill_kv = [&](int j0, int stg) {
        uint32_t so = base + oKV + (uint32_t)stg * 16384u;
#pragma unroll
        for (int w = 0; w < 8; w++) {
            int t = w * 128 + tid;
            int tile = t >> 9, r = (t >> 3) & 63, ch = t & 7;
            const __half* gb = (tile ? pVh : pKh) + (size_t)(j0 + r) * HD + ch * 8;
            uint32_t dst = so + (uint32_t)tile * 8192u + (uint32_t)r * 128u
                         + (uint32_t)(((ch ^ (r & 7)) & 7) << 4);
            CP16(dst, gb);
        }
    };
    auto fill_r64 = [&](int Bst) {
        int ringb = Bst & 255;
#pragma unroll
        for (int w = 0; w < 4; w++) {
            int t = w * 128 + tid;
            int r = t >> 3, ch = t & 7;
            int m = (Bst + r) & 2047;
            int rr = ringb + r;
            const __half* gb = pRh + (size_t)m * HD + ch * 8;
            uint32_t dst = base + oR + (uint32_t)rr * 128u
                         + (uint32_t)(((ch ^ (rr & 7)) & 7) << 4);
            CP16(dst, gb);
        }
    };

    // prologue group 1: Q tiles (64 rows x 4 tiles, 8192 B each)
#pragma unroll
    for (int w = 0; w < 16; w++) {
        int t = w * 128 + tid;
        int tile = t >> 9, r = (t >> 3) & 63, ch = t & 7;
        const __half* gb =
            ((tile == 0) ? pQUh : (tile == 1) ? pQUl : (tile == 2) ? pQVh : pQVl)
            + (size_t)r * HD + ch * 8;
        uint32_t dst = base + (uint32_t)tile * 8192u + (uint32_t)r * 128u
                     + (uint32_t)(((ch ^ (r & 7)) & 7) << 4);
        CP16(dst, gb);
    }
    asm volatile("cp.async.commit_group;" ::: "memory");
    // prologue group 2: KV_0 + band rows [B0, B0+128)
    const int B0 = 4096 - i0 - 64;
    fill_kv(0, 0);
    fill_r64(B0); fill_r64(B0 + 64);
    asm volatile("cp.async.commit_group;" ::: "memory");

    // hoist Q fragments
    asm volatile("cp.async.wait_group 1;" ::: "memory");
    __syncthreads();
    uint32_t fQUh[4][4], fQUl[4][4], fQVh[4][4], fQVl[4][4];
#pragma unroll
    for (int ks = 0; ks < 4; ks++) {
        int k0 = ks * 16;
        ldsA(fQUh[ks], base + 0u,     m0, k0, lane);
        ldsA(fQUl[ks], base + 8192u,  m0, k0, lane);
        ldsA(fQVh[ks], base + 16384u, m0, k0, lane);
        ldsA(fQVl[ks], base + 24576u, m0, k0, lane);
    }

    float mR0 = -1e30f, mR1 = -1e30f, lR0 = 0.f, lR1 = 0.f;
    float o[8][4];
#pragma unroll
    for (int nd = 0; nd < 8; nd++)
#pragma unroll
        for (int q = 0; q < 4; q++) o[nd][q] = 0.f;

    const int nIt = i0 / 64 + 1;
    for (int c = 0; c < nIt; c++) {
        const int j0 = c * 64;
        const int Bc = 64 * c + B0;
        asm volatile("cp.async.wait_group 0;" ::: "memory");
        __syncthreads();
        if (c + 1 < nIt) {
            fill_kv(j0 + 64, (c + 1) & 1);
            fill_r64(Bc + 128);
            asm volatile("cp.async.commit_group;" ::: "memory");
        }

        const bool act = (j0 <= i0 + m0 + 15);
        const uint32_t kst = base + oKV + (uint32_t)(c & 1) * 16384u;
        const uint32_t tKh = kst, tVh = kst + 8192u;

        float sF[8][4];
        if (act) {
            // GEMM2: band -> warp-private sS
            float aT[5][2][4];
#pragma unroll
            for (int b = 0; b < 5; b++)
#pragma unroll
                for (int hf = 0; hf < 2; hf++)
#pragma unroll
                    for (int q = 0; q < 4; q++) aT[b][hf][q] = 0.f;
#pragma unroll
            for (int ks = 0; ks < 4; ks++) {
                int k0 = ks * 16;
#pragma unroll
                for (int b = 0; b < 5; b++) {
                    int rT0 = (Bc + 48 - m0 + b * 16) & 255;
                    uint32_t bh[4];
                    ldsB(bh, base + oR, rT0, k0, lane);
                    mma_f16(aT[b][0], fQVh[ks], bh); mma_f16(aT[b][1], fQVh[ks], bh + 2);
                    mma_f16(aT[b][0], fQVl[ks], bh); mma_f16(aT[b][1], fQVl[ks], bh + 2);
                }
            }
#pragma unroll
            for (int b = 0; b < 5; b++)
#pragma unroll
                for (int hf = 0; hf < 2; hf++) {
                    int j0e = b * 16 + hf * 8 + fc + fr - 15;
                    if ((unsigned)j0e < 64u)       sS[il0 * 66 + j0e]     = aT[b][hf][0];
                    if ((unsigned)(j0e + 1) < 64u) sS[il0 * 66 + j0e + 1] = aT[b][hf][1];
                    int j1e = j0e + 8;
                    if ((unsigned)j1e < 64u)       sS[il1 * 66 + j1e]     = aT[b][hf][2];
                    if ((unsigned)(j1e + 1) < 64u) sS[il1 * 66 + j1e + 1] = aT[b][hf][3];
                }

            // GEMM1: content scores
#pragma unroll
            for (int f = 0; f < 8; f++)
#pragma unroll
                for (int q = 0; q < 4; q++) sF[f][q] = 0.f;
#pragma unroll
            for (int ks = 0; ks < 4; ks++) {
                int k0 = ks * 16;
#pragma unroll
                for (int nb = 0; nb < 4; nb++) {
                    uint32_t bh[4];
                    ldsB(bh, tKh, nb * 16, k0, lane);
                    mma_f16(sF[nb * 2], fQUh[ks], bh); mma_f16(sF[nb * 2 + 1], fQUh[ks], bh + 2);
                    mma_f16(sF[nb * 2], fQUl[ks], bh); mma_f16(sF[nb * 2 + 1], fQUl[ks], bh + 2);
                }
            }
            __syncwarp();

            // softmax (quad-local)
            float sv0[8][2], sv1[8][2];
            float mx0 = -1e30f, mx1 = -1e30f;
#pragma unroll
            for (int f = 0; f < 8; f++) {
                float2 b0 = *(float2*)&sS[il0 * 66 + f * 8 + fc];
                float2 b1 = *(float2*)&sS[il1 * 66 + f * 8 + fc];
                int jc = f * 8 + fc;
                float s00 = (sF[f][0] + b0.x) * SCALE;
                float s01 = (sF[f][1] + b0.y) * SCALE;
                float s10 = (sF[f][2] + b1.x) * SCALE;
                float s11 = (sF[f][3] + b1.y) * SCALE;
                if (j0 + jc     > i0 + il0) s00 = -1e30f;
                if (j0 + jc + 1 > i0 + il0) s01 = -1e30f;
                if (j0 + jc     > i0 + il1) s10 = -1e30f;
                if (j0 + jc + 1 > i0 + il1) s11 = -1e30f;
                sv0[f][0] = s00; sv0[f][1] = s01;
                sv1[f][0] = s10; sv1[f][1] = s11;
                mx0 = fmaxf(mx0, fmaxf(s00, s01));
                mx1 = fmaxf(mx1, fmaxf(s10, s11));
            }
            mx0 = fmaxf(mx0, __shfl_xor_sync(0xffffffffu, mx0, 1));
            mx0 = fmaxf(mx0, __shfl_xor_sync(0xffffffffu, mx0, 2));
            mx1 = fmaxf(mx1, __shfl_xor_sync(0xffffffffu, mx1, 1));
            mx1 = fmaxf(mx1, __shfl_xor_sync(0xffffffffu, mx1, 2));
            float mNew0 = fmaxf(mR0, mx0), mNew1 = fmaxf(mR1, mx1);
            float corr0 = __expf(mR0 - mNew0), corr1 = __expf(mR1 - mNew1);
            mR0 = mNew0; mR1 = mNew1;
            float rs0 = 0.f, rs1 = 0.f;
            float pv0[8][2], pv1[8][2];
#pragma unroll
            for (int f = 0; f < 8; f++) {
                pv0[f][0] = __expf(sv0[f][0] - mNew0);
                pv0[f][1] = __expf(sv0[f][1] - mNew0);
                pv1[f][0] = __expf(sv1[f][0] - mNew1);
                pv1[f][1] = __expf(sv1[f][1] - mNew1);
                rs0 += pv0[f][0] + pv0[f][1];
                rs1 += pv1[f][0] + pv1[f][1];
            }
            rs0 += __shfl_xor_sync(0xffffffffu, rs0, 1);
            rs0 += __shfl_xor_sync(0xffffffffu, rs0, 2);
            rs1 += __shfl_xor_sync(0xffffffffu, rs1, 1);
            rs1 += __shfl_xor_sync(0xffffffffu, rs1, 2);
            lR0 = lR0 * corr0 + rs0;
            lR1 = lR1 * corr1 + rs1;

            uint32_t ph[4][4], pl[4][4];
#pragma unroll
            for (int ks = 0; ks < 4; ks++) {
                split2h(pv0[2 * ks][0],     pv0[2 * ks][1],     ph[ks][0], pl[ks][0]);
                split2h(pv1[2 * ks][0],     pv1[2 * ks][1],     ph[ks][1], pl[ks][1]);
                split2h(pv0[2 * ks + 1][0], pv0[2 * ks + 1][1], ph[ks][2], pl[ks][2]);
                split2h(pv1[2 * ks + 1][0], pv1[2 * ks + 1][1], ph[ks][3], pl[ks][3]);
            }

            // GEMM3: O = O*corr + P*V
#pragma unroll
            for (int nd = 0; nd < 8; nd++) {
                o[nd][0] *= corr0; o[nd][1] *= corr0;
                o[nd][2] *= corr1; o[nd][3] *= corr1;
            }
#pragma unroll
            for (int ks = 0; ks < 4; ks++) {
                int k0 = ks * 16;
#pragma unroll
                for (int nd2 = 0; nd2 < 4; nd2++) {
                    uint32_t bh[4];
                    ldsBT(bh, tVh, nd2 * 16, k0, lane);
                    float* o0 = o[nd2 * 2 + 0];
                    float* o1 = o[nd2 * 2 + 1];
                    mma_f16(o0, ph[ks], bh); mma_f16(o1, ph[ks], bh + 2);
                    mma_f16(o0, pl[ks], bh); mma_f16(o1, pl[ks], bh + 2);
                }
            }
        }
    }

    // epilogue
    {
        float inv0 = 1.f / lR0, inv1 = 1.f / lR1;
#pragma unroll
        for (int nd = 0; nd < 8; nd++) {
            int col = h * HD + nd * 8 + fc;
            uint32_t hh, ll;
            split2h(o[nd][0] * inv0, o[nd][1] * inv0, hh, ll);
            size_t w = ((size_t)(i0 + il0) * V_DIM + col) >> 1;
            ((uint32_t*)g_ah)[w] = hh; ((uint32_t*)g_al)[w] = ll;
            split2h(o[nd][2] * inv1, o[nd][3] * inv1, hh, ll);
            w = ((size_t)(i0 + il1) * V_DIM + col) >> 1;
            ((uint32_t*)g_ah)[w] = hh; ((uint32_t*)g_al)[w] = ll;
        }
    }
}

// ---------------------------------------------------------------------------
extern "C" void kernel_launch(void* const* d_in, const int* in_sizes, int n_in,
                              void* d_out, int out_size)
{
    const float* x    = (const float*)d_in[0];
    const float* Wqkv = (const float*)d_in[1];
    const float* Wout = (const float*)d_in[2];
    const float* Wpos = (const float*)d_in[3];
    const float* u    = (const float*)d_in[4];
    const float* v    = (const float*)d_in[5];
    const float* rel  = (const float*)d_in[6];
    float* out = (float*)d_out;

    void *xh, *xl, *wqh, *rh, *rl, *wph, *ah, *al, *woh;
    cudaGetSymbolAddress(&xh,  g_xh);  cudaGetSymbolAddress(&xl,  g_xl);
    cudaGetSymbolAddress(&wqh, g_wqh);
    cudaGetSymbolAddress(&rh,  g_rh);  cudaGetSymbolAddress(&rl,  g_rl);
    cudaGetSymbolAddress(&wph, g_wph);
    cudaGetSymbolAddress(&ah,  g_ah);  cudaGetSymbolAddress(&al,  g_al);
    cudaGetSymbolAddress(&woh, g_woh);

    cudaFuncSetAttribute(flash_xl_mma,
                         cudaFuncAttributeMaxDynamicSharedMemorySize, FL_SMEM);
    cudaFuncSetAttribute(gemm_f16x2<0>,
                         cudaFuncAttributeMaxDynamicSharedMemorySize, GEMM_SMEM);
    cudaFuncSetAttribute(gemm_f16x2<3>,
                         cudaFuncAttributeMaxDynamicSharedMemorySize, GEMM_SMEM);

    // 1) split all fp32 inputs
    split_all<<<9216, 256>>>((const float4*)x, (const float4*)Wqkv,
                             (const float4*)rel, (const float4*)Wpos,
                             (const float4*)Wout);

    // 2) merged qkv + pos projections (blocks 0-11: qkv; 12-15: pos)
    gemm_f16x2<3><<<dim3(16, 16), 256, GEMM_SMEM>>>(
        (const __half*)xh, (const __half*)xl, (const __half*)wqh,
        (const __half*)rh, (const __half*)rl, (const __half*)wph,
        nullptr, u, v, S_LEN, QKV_LD, V_DIM);

    // 3) fused attention -> g_ah/g_al (fp16 hi/lo); 64-row CTAs, 2/SM
    flash_xl_mma<<<dim3(NH, S_LEN / 64), 128, FL_SMEM>>>();

    // 4) out = attn @ Wout^T -> fp32 d_out
    gemm_f16x2<0><<<dim3(V_DIM / 256, S_LEN / 128), 256, GEMM_SMEM>>>(
        (const __half*)ah, (const __half*)al, (const __half*)woh,
        nullptr, nullptr, nullptr,
        out, nullptr, nullptr, S_LEN, V_DIM, V_DIM);
}

// round 17
// speedup vs baseline: 1.1014x; 1.1014x over previous
#include <cuda_runtime.h>
#include <cuda_fp16.h>
#include <cstdint>

#define S_LEN 2048
#define V_DIM 1024
#define NH    16
#define HD    64
#define QKV_LD 3072
#define SCALE 0.125f

// ---------------- scratch (__device__ globals; no allocation allowed) ------
__device__ __align__(256) __half g_xh[S_LEN * V_DIM],  g_xl[S_LEN * V_DIM];
__device__ __align__(256) __half g_wqh[QKV_LD * V_DIM];
__device__ __align__(256) __half g_rh[S_LEN * V_DIM],  g_rl[S_LEN * V_DIM];
__device__ __align__(256) __half g_wph[V_DIM * V_DIM];
__device__ __align__(256) __half g_ah[S_LEN * V_DIM];     // attn out (hi only)
__device__ __align__(256) __half g_woh[V_DIM * V_DIM];

// per-head fp16 tensors for flash: layout [H][S][64]
#define HSD (NH * S_LEN * HD)
__device__ __align__(256) __half g_quh[HSD], g_qul[HSD];   // q + u (hi/lo)
__device__ __align__(256) __half g_qvh[HSD], g_qvl[HSD];   // q + v (hi/lo)
__device__ __align__(256) __half g_kh[HSD];                // k (hi only)
__device__ __align__(256) __half g_vh[HSD];                // v (hi only)
__device__ __align__(256) __half g_rph[HSD];               // pos (hi only)

// ---------------- helpers ---------------------------------------------------
__device__ __forceinline__ uint32_t s2u(const void* p) {
    uint32_t a;
    asm("{ .reg .u64 t; cvta.to.shared.u64 t, %1; cvt.u32.u64 %0, t; }"
        : "=r"(a) : "l"(p));
    return a;
}
__device__ __forceinline__ void ldm4(uint32_t* f, uint32_t addr) {
    asm volatile("ldmatrix.sync.aligned.m8n8.x4.shared.b16 {%0,%1,%2,%3}, [%4];"
                 : "=r"(f[0]), "=r"(f[1]), "=r"(f[2]), "=r"(f[3]) : "r"(addr));
}
__device__ __forceinline__ void ldm4t(uint32_t* f, uint32_t addr) {
    asm volatile("ldmatrix.sync.aligned.m8n8.x4.trans.shared.b16 {%0,%1,%2,%3}, [%4];"
                 : "=r"(f[0]), "=r"(f[1]), "=r"(f[2]), "=r"(f[3]) : "r"(addr));
}
__device__ __forceinline__ void mma_f16(float* d, const uint32_t* a,
                                        const uint32_t* b) {
    asm volatile(
        "mma.sync.aligned.m16n8k16.row.col.f32.f16.f16.f32 "
        "{%0,%1,%2,%3}, {%4,%5,%6,%7}, {%8,%9}, {%0,%1,%2,%3};"
        : "+f"(d[0]), "+f"(d[1]), "+f"(d[2]), "+f"(d[3])
        : "r"(a[0]), "r"(a[1]), "r"(a[2]), "r"(a[3]), "r"(b[0]), "r"(b[1]));
}
__device__ __forceinline__ void ldsA(uint32_t* f, uint32_t tile, int m0, int k0,
                                     int lane) {
    int r = lane & 7, g = lane >> 3;
    int row = m0 + r + (g & 1) * 8;
    int kch = (k0 >> 3) + (g >> 1);
    ldm4(f, tile + row * 128 + (((kch ^ (row & 7)) & 7) << 4));
}
__device__ __forceinline__ void ldsB(uint32_t* f, uint32_t tile, int n0, int k0,
                                     int lane) {
    int r = lane & 7, g = lane >> 3;
    int row = n0 + r + (g >> 1) * 8;
    int kch = (k0 >> 3) + (g & 1);
    ldm4(f, tile + row * 128 + (((kch ^ (row & 7)) & 7) << 4));
}
__device__ __forceinline__ void ldsBT(uint32_t* f, uint32_t tile, int n0, int k0,
                                      int lane) {
    int r = lane & 7, g = lane >> 3;
    int row = k0 + r + (g & 1) * 8;
    int bch = (n0 + (g >> 1) * 8) >> 3;
    ldm4t(f, tile + row * 128 + (((bch ^ (row & 7)) & 7) << 4));
}
__device__ __forceinline__ uint32_t pack2h(float a, float b) {
    __half2 p = __floats2half2_rn(a, b);
    return *(uint32_t*)&p;
}
__device__ __forceinline__ void split2h(float a, float b, uint32_t& hi,
                                        uint32_t& lo) {
    __half ah = __float2half_rn(a), bh = __float2half_rn(b);
    __half al = __float2half_rn(a - __half2float(ah));
    __half bl = __float2half_rn(b - __half2float(bh));
    hi = (uint32_t)*(uint16_t*)&ah | ((uint32_t)*(uint16_t*)&bh << 16);
    lo = (uint32_t)*(uint16_t*)&al | ((uint32_t)*(uint16_t*)&bl << 16);
}
#define CP16(dst, src)                                                         \
    asm volatile("cp.async.cg.shared.global [%0], [%1], 16;"                   \
                 :: "r"(dst), "l"(src) : "memory")

// ---------------- fused input split: x | Wqkv | rel | Wpos | Wout ----------
__global__ __launch_bounds__(256) void split_all(
    const float4* __restrict__ x, const float4* __restrict__ wq,
    const float4* __restrict__ rel, const float4* __restrict__ wp,
    const float4* __restrict__ wo)
{
    int i = blockIdx.x * 256 + threadIdx.x;
    const float4* src; uint32_t* H; uint32_t* L; int li; bool wl;
    if (i < 524288)       { src = x;   H = (uint32_t*)g_xh;  L = (uint32_t*)g_xl; li = i; wl = true; }
    else if (i < 1310720) { src = wq;  H = (uint32_t*)g_wqh; L = nullptr; li = i - 524288;  wl = false; }
    else if (i < 1835008) { src = rel; H = (uint32_t*)g_rh;  L = (uint32_t*)g_rl; li = i - 1310720; wl = true; }
    else if (i < 2097152) { src = wp;  H = (uint32_t*)g_wph; L = nullptr; li = i - 1835008; wl = false; }
    else                  { src = wo;  H = (uint32_t*)g_woh; L = nullptr; li = i - 2097152; wl = false; }
    float4 v = src[li];
    uint32_t h0, l0, h1, l1;
    split2h(v.x, v.y, h0, l0);
    split2h(v.z, v.w, h1, l1);
    H[2 * li] = h0; H[2 * li + 1] = h1;
    if (wl) { L[2 * li] = l0; L[2 * li + 1] = l1; }
}

// ---------------------------------------------------------------------------
// Merged projection GEMM (R13 config): 512 threads / 16 warps, 32x32 warp
// tile, 4-stage cp.async. blockIdx.x<24: qkv (A=x hi+lo, B=Wqkv hi);
// else: pos (A=rel hi+lo, B=Wpos hi). K=1024.
// ---------------------------------------------------------------------------
#define GSTAGE 49152
#define GEMM_SMEM (4 * GSTAGE + 1024)

__global__ __launch_bounds__(512, 1) void gemm_proj(
    const __half* __restrict__ Ah, const __half* __restrict__ Al,
    const __half* __restrict__ Bh,
    const __half* __restrict__ Ah2, const __half* __restrict__ Al2,
    const __half* __restrict__ Bh2,
    const float* __restrict__ u_vec, const float* __restrict__ v_vec, int K)
{
    extern __shared__ char smem[];
    uint32_t tiles = (s2u(smem) + 1023u) & ~1023u;
    const int tid = threadIdx.x;
    const int lane = tid & 31, wid = tid >> 5;
    const int wm = wid & 3, wn = wid >> 2;
    const int bm = blockIdx.y * 128;

    bool seg2 = false;
    int bn;
    const __half *pA, *pL, *pB;
    if (blockIdx.x >= 24) {
        seg2 = true;
        bn = (blockIdx.x - 24) * 128;
        pA = Ah2; pL = Al2; pB = Bh2;
    } else {
        bn = blockIdx.x * 128;
        pA = Ah; pL = Al; pB = Bh;
    }

    const __half* gsrc[6];
    uint32_t sdst[6];
#pragma unroll
    for (int u = 0; u < 6; u++) {
        int idx = u * 512 + tid;
        int tile = idx >> 10, row = (idx >> 3) & 127, cc = idx & 7;
        const __half* bp = (tile == 0) ? pA : (tile == 1) ? pL : pB;
        int gr = ((tile < 2) ? bm : bn) + row;
        gsrc[u] = bp + (size_t)gr * K + cc * 8;
        sdst[u] = tiles + tile * 16384u + row * 128u
                + (uint32_t)((cc ^ (row & 7)) << 4);
    }
    const int NC = K >> 6;

    float acc[2][4][4];
#pragma unroll
    for (int mi = 0; mi < 2; mi++)
#pragma unroll
        for (int ni = 0; ni < 4; ni++)
#pragma unroll
            for (int q = 0; q < 4; q++) acc[mi][ni][q] = 0.f;

#pragma unroll
    for (int s = 0; s < 3; s++) {
        uint32_t so = (uint32_t)s * GSTAGE;
        int ke = s << 6;
#pragma unroll
        for (int u = 0; u < 6; u++) CP16(sdst[u] + so, gsrc[u] + ke);
        asm volatile("cp.async.commit_group;" ::: "memory");
    }

    for (int c = 0; c < NC; c++) {
        int rem = NC - 1 - c;
        if (rem >= 2)      asm volatile("cp.async.wait_group 2;" ::: "memory");
        else if (rem == 1) asm volatile("cp.async.wait_group 1;" ::: "memory");
        else               asm volatile("cp.async.wait_group 0;" ::: "memory");
        __syncthreads();
        if (c + 3 < NC) {
            uint32_t so = (uint32_t)((c + 3) & 3) * GSTAGE;
            int ke = (c + 3) << 6;
#pragma unroll
            for (int u = 0; u < 6; u++) CP16(sdst[u] + so, gsrc[u] + ke);
            asm volatile("cp.async.commit_group;" ::: "memory");
        }

        uint32_t st = (uint32_t)(c & 3) * GSTAGE;
        uint32_t tAh = tiles + st, tAl = tAh + 16384u, tBh = tAl + 16384u;
#pragma unroll
        for (int ks = 0; ks < 4; ks++) {
            int k0 = ks * 16;
            uint32_t ah[8], al[8], bb[8];
            ldsA(&ah[0], tAh, wm * 32,      k0, lane);
            ldsA(&ah[4], tAh, wm * 32 + 16, k0, lane);
            ldsB(&bb[0], tBh, wn * 32,      k0, lane);
            ldsB(&bb[4], tBh, wn * 32 + 16, k0, lane);
#pragma unroll
            for (int mi = 0; mi < 2; mi++)
#pragma unroll
                for (int ni = 0; ni < 4; ni++)
                    mma_f16(acc[mi][ni], &ah[mi * 4], &bb[ni * 2]);
            ldsA(&al[0], tAl, wm * 32,      k0, lane);
            ldsA(&al[4], tAl, wm * 32 + 16, k0, lane);
#pragma unroll
            for (int mi = 0; mi < 2; mi++)
#pragma unroll
                for (int ni = 0; ni < 4; ni++)
                    mma_f16(acc[mi][ni], &al[mi * 4], &bb[ni * 2]);
        }
    }

    const int r0 = lane >> 2, c0 = (lane & 3) * 2;
#pragma unroll
    for (int mi = 0; mi < 2; mi++) {
        int gm = bm + wm * 32 + mi * 16;
#pragma unroll
        for (int ni = 0; ni < 4; ni++) {
            int gn = bn + wn * 32 + ni * 8 + c0;
            if (seg2) {
                int hd_ = gn & 1023;
                size_t w0 = (((size_t)(hd_ >> 6) * S_LEN + gm + r0) * HD
                             + (hd_ & 63)) >> 1;
                size_t w1 = w0 + 256;
                ((uint32_t*)g_rph)[w0] = pack2h(acc[mi][ni][0], acc[mi][ni][1]);
                ((uint32_t*)g_rph)[w1] = pack2h(acc[mi][ni][2], acc[mi][ni][3]);
            } else {
                int sec = gn >> 10;
                int hd_ = gn & 1023;
                size_t w0 = (((size_t)(hd_ >> 6) * S_LEN + gm + r0) * HD
                             + (hd_ & 63)) >> 1;
                size_t w1 = w0 + 256;
                uint32_t hh, ll;
                if (sec == 0) {
                    float2 uu = *(const float2*)&u_vec[hd_];
                    float2 vv = *(const float2*)&v_vec[hd_];
                    split2h(acc[mi][ni][0] + uu.x, acc[mi][ni][1] + uu.y, hh, ll);
                    ((uint32_t*)g_quh)[w0] = hh; ((uint32_t*)g_qul)[w0] = ll;
                    split2h(acc[mi][ni][2] + uu.x, acc[mi][ni][3] + uu.y, hh, ll);
                    ((uint32_t*)g_quh)[w1] = hh; ((uint32_t*)g_qul)[w1] = ll;
                    split2h(acc[mi][ni][0] + vv.x, acc[mi][ni][1] + vv.y, hh, ll);
                    ((uint32_t*)g_qvh)[w0] = hh; ((uint32_t*)g_qvl)[w0] = ll;
                    split2h(acc[mi][ni][2] + vv.x, acc[mi][ni][3] + vv.y, hh, ll);
                    ((uint32_t*)g_qvh)[w1] = hh; ((uint32_t*)g_qvl)[w1] = ll;
                } else if (sec == 1) {
                    ((uint32_t*)g_kh)[w0] = pack2h(acc[mi][ni][0], acc[mi][ni][1]);
                    ((uint32_t*)g_kh)[w1] = pack2h(acc[mi][ni][2], acc[mi][ni][3]);
                } else {
                    ((uint32_t*)g_vh)[w0] = pack2h(acc[mi][ni][0], acc[mi][ni][1]);
                    ((uint32_t*)g_vh)[w1] = pack2h(acc[mi][ni][2], acc[mi][ni][3]);
                }
            }
        }
    }
}

// ---------------------------------------------------------------------------
// Output GEMM, A hi-only: C[M,N] = A[M,K] * B[N,K]^T (fp32 C).
// 512 threads / 16 warps, 32x32 warp tile, 4-stage cp.async (32 KB/stage).
// ---------------------------------------------------------------------------
#define OSTAGE 32768
#define OUT_SMEM (4 * OSTAGE + 1024)

__global__ __launch_bounds__(512, 1) void gemm_out(
    const __half* __restrict__ Ah, const __half* __restrict__ Bh,
    float* __restrict__ C, int N, int K)
{
    extern __shared__ char smem[];
    uint32_t tiles = (s2u(smem) + 1023u) & ~1023u;
    const int tid = threadIdx.x;
    const int lane = tid & 31, wid = tid >> 5;
    const int wm = wid & 3, wn = wid >> 2;
    const int bm = blockIdx.y * 128, bn = blockIdx.x * 128;

    const __half* gsrc[4];
    uint32_t sdst[4];
#pragma unroll
    for (int u = 0; u < 4; u++) {
        int idx = u * 512 + tid;                 // 0..2047
        int tile = idx >> 10, row = (idx >> 3) & 127, cc = idx & 7;
        gsrc[u] = (tile ? Bh : Ah) + (size_t)((tile ? bn : bm) + row) * K + cc * 8;
        sdst[u] = tiles + (uint32_t)tile * 16384u + row * 128u
                + (uint32_t)((cc ^ (row & 7)) << 4);
    }
    const int NC = K >> 6;

    float acc[2][4][4];
#pragma unroll
    for (int mi = 0; mi < 2; mi++)
#pragma unroll
        for (int ni = 0; ni < 4; ni++)
#pragma unroll
            for (int q = 0; q < 4; q++) acc[mi][ni][q] = 0.f;

#pragma unroll
    for (int s = 0; s < 3; s++) {
        uint32_t so = (uint32_t)s * OSTAGE;
        int ke = s << 6;
#pragma unroll
        for (int u = 0; u < 4; u++) CP16(sdst[u] + so, gsrc[u] + ke);
        asm volatile("cp.async.commit_group;" ::: "memory");
    }

    for (int c = 0; c < NC; c++) {
        int rem = NC - 1 - c;
        if (rem >= 2)      asm volatile("cp.async.wait_group 2;" ::: "memory");
        else if (rem == 1) asm volatile("cp.async.wait_group 1;" ::: "memory");
        else               asm volatile("cp.async.wait_group 0;" ::: "memory");
        __syncthreads();
        if (c + 3 < NC) {
            uint32_t so = (uint32_t)((c + 3) & 3) * OSTAGE;
            int ke = (c + 3) << 6;
#pragma unroll
            for (int u = 0; u < 4; u++) CP16(sdst[u] + so, gsrc[u] + ke);
            asm volatile("cp.async.commit_group;" ::: "memory");
        }

        uint32_t st = (uint32_t)(c & 3) * OSTAGE;
        uint32_t tAh = tiles + st, tBh = tAh + 16384u;
#pragma unroll
        for (int ks = 0; ks < 4; ks++) {
            int k0 = ks * 16;
            uint32_t ah[8], bb[8];
            ldsA(&ah[0], tAh, wm * 32,      k0, lane);
            ldsA(&ah[4], tAh, wm * 32 + 16, k0, lane);
            ldsB(&bb[0], tBh, wn * 32,      k0, lane);
            ldsB(&bb[4], tBh, wn * 32 + 16, k0, lane);
#pragma unroll
            for (int mi = 0; mi < 2; mi++)
#pragma unroll
                for (int ni = 0; ni < 4; ni++)
                    mma_f16(acc[mi][ni], &ah[mi * 4], &bb[ni * 2]);
        }
    }

    const int r0 = lane >> 2, c0 = (lane & 3) * 2;
#pragma unroll
    for (int mi = 0; mi < 2; mi++) {
        int gm = bm + wm * 32 + mi * 16;
#pragma unroll
        for (int ni = 0; ni < 4; ni++) {
            int gn = bn + wn * 32 + ni * 8 + c0;
            float* p0 = C + (size_t)(gm + r0) * N + gn;
            float* p1 = C + (size_t)(gm + r0 + 8) * N + gn;
            *(float2*)p0 = make_float2(acc[mi][ni][0], acc[mi][ni][1]);
            *(float2*)p1 = make_float2(acc[mi][ni][2], acc[mi][ni][3]);
        }
    }
}

// ---------------------------------------------------------------------------
// Flash-attention, Transformer-XL shift — fp16 x2, 64-row CTAs, 2 CTA/SM.
// Grid (NH, 32). CTA = 64 i-rows; 4 warps; warp owns 16 rows x 64 j x 64 d.
// smem 115200 B. One __syncthreads per j-iter.   (R13, epilogue hi-only)
// ---------------------------------------------------------------------------
#define oKV 32768           /* stage*16384: Kh @0, Vh @8192 */
#define oR  65536           /* Rh 256-row ring (hi only)    */
#define oS  98304           /* fp32 [64][66] warp-private strips */
#define FL_SMEM 115200

__global__ __launch_bounds__(128) void flash_xl_mma()
{
    extern __shared__ char fsm[];
    const uint32_t base = s2u(fsm);
    float* sS = (float*)(fsm + oS);

    const int h   = blockIdx.x;
    const int i0  = 64 * (int)(gridDim.y - 1 - blockIdx.y);   // heavy first
    const int tid = threadIdx.x;
    const int lane = tid & 31, wid = tid >> 5;
    const int m0 = wid * 16;
    const int fr = lane >> 2, fc = (lane & 3) * 2;
    const int il0 = m0 + fr, il1 = il0 + 8;

    const size_t hb = (size_t)h * (S_LEN * HD);
    const __half* pQUh = g_quh + hb + (size_t)i0 * HD;
    const __half* pQUl = g_qul + hb + (size_t)i0 * HD;
    const __half* pQVh = g_qvh + hb + (size_t)i0 * HD;
    const __half* pQVl = g_qvl + hb + (size_t)i0 * HD;
    const __half* pKh  = g_kh  + hb;
    const __half* pVh  = g_vh  + hb;
    const __half* pRh  = g_rph + hb;

    auto fill_kv = [&](int j0, int stg) {
        uint32_t so = base + oKV + (uint32_t)stg * 16384u;
#pragma unroll
        for (int w = 0; w < 8; w++) {
            int t = w * 128 + tid;
            int tile = t >> 9, r = (t >> 3) & 63, ch = t & 7;
            const __half* gb = (tile ? pVh : pKh) + (size_t)(j0 + r) * HD + ch * 8;
            uint32_t dst = so + (uint32_t)tile * 8192u + (uint32_t)r * 128u
                         + (uint32_t)(((ch ^ (r & 7)) & 7) << 4);
            CP16(dst, gb);
        }
    };
    auto fill_r64 = [&](int Bst) {
        int ringb = Bst & 255;
#pragma unroll
        for (int w = 0; w < 4; w++) {
            int t = w * 128 + tid;
            int r = t >> 3, ch = t & 7;
            int m = (Bst + r) & 2047;
            int rr = ringb + r;
            const __half* gb = pRh + (size_t)m * HD + ch * 8;
            uint32_t dst = base + oR + (uint32_t)rr * 128u
                         + (uint32_t)(((ch ^ (rr & 7)) & 7) << 4);
            CP16(dst, gb);
        }
    };

    // prologue group 1: Q tiles (64 rows x 4 tiles, 8192 B each)
#pragma unroll
    for (int w = 0; w < 16; w++) {
        int t = w * 128 + tid;
        int tile = t >> 9, r = (t >> 3) & 63, ch = t & 7;
        const __half* gb =
            ((tile == 0) ? pQUh : (tile == 1) ? pQUl : (tile == 2) ? pQVh : pQVl)
            + (size_t)r * HD + ch * 8;
        uint32_t dst = base + (uint32_t)tile * 8192u + (uint32_t)r * 128u
                     + (uint32_t)(((ch ^ (r & 7)) & 7) << 4);
        CP16(dst, gb);
    }
    asm volatile("cp.async.commit_group;" ::: "memory");
    // prologue group 2: KV_0 + band rows [B0, B0+128)
    const int B0 = 4096 - i0 - 64;
    fill_kv(0, 0);
    fill_r64(B0); fill_r64(B0 + 64);
    asm volatile("cp.async.commit_group;" ::: "memory");

    // hoist Q fragments
    asm volatile("cp.async.wait_group 1;" ::: "memory");
    __syncthreads();
    uint32_t fQUh[4][4], fQUl[4][4], fQVh[4][4], fQVl[4][4];
#pragma unroll
    for (int ks = 0; ks < 4; ks++) {
        int k0 = ks * 16;
        ldsA(fQUh[ks], base + 0u,     m0, k0, lane);
        ldsA(fQUl[ks], base + 8192u,  m0, k0, lane);
        ldsA(fQVh[ks], base + 16384u, m0, k0, lane);
        ldsA(fQVl[ks], base + 24576u, m0, k0, lane);
    }

    float mR0 = -1e30f, mR1 = -1e30f, lR0 = 0.f, lR1 = 0.f;
    float o[8][4];
#pragma unroll
    for (int nd = 0; nd < 8; nd++)
#pragma unroll
        for (int q = 0; q < 4; q++) o[nd][q] = 0.f;

    const int nIt = i0 / 64 + 1;
    for (int c = 0; c < nIt; c++) {
        const int j0 = c * 64;
        const int Bc = 64 * c + B0;
        asm volatile("cp.async.wait_group 0;" ::: "memory");
        __syncthreads();
        if (c + 1 < nIt) {
            fill_kv(j0 + 64, (c + 1) & 1);
            fill_r64(Bc + 128);
            asm volatile("cp.async.commit_group;" ::: "memory");
        }

        const bool act = (j0 <= i0 + m0 + 15);
        const uint32_t kst = base + oKV + (uint32_t)(c & 1) * 16384u;
        const uint32_t tKh = kst, tVh = kst + 8192u;

        float sF[8][4];
        if (act) {
            // GEMM2: band -> warp-private sS
            float aT[5][2][4];
#pragma unroll
            for (int b = 0; b < 5; b++)
#pragma unroll
                for (int hf = 0; hf < 2; hf++)
#pragma unroll
                    for (int q = 0; q < 4; q++) aT[b][hf][q] = 0.f;
#pragma unroll
            for (int ks = 0; ks < 4; ks++) {
                int k0 = ks * 16;
#pragma unroll
                for (int b = 0; b < 5; b++) {
                    int rT0 = (Bc + 48 - m0 + b * 16) & 255;
                    uint32_t bh[4];
                    ldsB(bh, base + oR, rT0, k0, lane);
                    mma_f16(aT[b][0], fQVh[ks], bh); mma_f16(aT[b][1], fQVh[ks], bh + 2);
                    mma_f16(aT[b][0], fQVl[ks], bh); mma_f16(aT[b][1], fQVl[ks], bh + 2);
                }
            }
#pragma unroll
            for (int b = 0; b < 5; b++)
#pragma unroll
                for (int hf = 0; hf < 2; hf++) {
                    int j0e = b * 16 + hf * 8 + fc + fr - 15;
                    if ((unsigned)j0e < 64u)       sS[il0 * 66 + j0e]     = aT[b][hf][0];
                    if ((unsigned)(j0e + 1) < 64u) sS[il0 * 66 + j0e + 1] = aT[b][hf][1];
                    int j1e = j0e + 8;
                    if ((unsigned)j1e < 64u)       sS[il1 * 66 + j1e]     = aT[b][hf][2];
                    if ((unsigned)(j1e + 1) < 64u) sS[il1 * 66 + j1e + 1] = aT[b][hf][3];
                }

            // GEMM1: content scores
#pragma unroll
            for (int f = 0; f < 8; f++)
#pragma unroll
                for (int q = 0; q < 4; q++) sF[f][q] = 0.f;
#pragma unroll
            for (int ks = 0; ks < 4; ks++) {
                int k0 = ks * 16;
#pragma unroll
                for (int nb = 0; nb < 4; nb++) {
                    uint32_t bh[4];
                    ldsB(bh, tKh, nb * 16, k0, lane);
                    mma_f16(sF[nb * 2], fQUh[ks], bh); mma_f16(sF[nb * 2 + 1], fQUh[ks], bh + 2);
                    mma_f16(sF[nb * 2], fQUl[ks], bh); mma_f16(sF[nb * 2 + 1], fQUl[ks], bh + 2);
                }
            }
            __syncwarp();

            // softmax (quad-local)
            float sv0[8][2], sv1[8][2];
            float mx0 = -1e30f, mx1 = -1e30f;
#pragma unroll
            for (int f = 0; f < 8; f++) {
                float2 b0 = *(float2*)&sS[il0 * 66 + f * 8 + fc];
                float2 b1 = *(float2*)&sS[il1 * 66 + f * 8 + fc];
                int jc = f * 8 + fc;
                float s00 = (sF[f][0] + b0.x) * SCALE;
                float s01 = (sF[f][1] + b0.y) * SCALE;
                float s10 = (sF[f][2] + b1.x) * SCALE;
                float s11 = (sF[f][3] + b1.y) * SCALE;
                if (j0 + jc     > i0 + il0) s00 = -1e30f;
                if (j0 + jc + 1 > i0 + il0) s01 = -1e30f;
                if (j0 + jc     > i0 + il1) s10 = -1e30f;
                if (j0 + jc + 1 > i0 + il1) s11 = -1e30f;
                sv0[f][0] = s00; sv0[f][1] = s01;
                sv1[f][0] = s10; sv1[f][1] = s11;
                mx0 = fmaxf(mx0, fmaxf(s00, s01));
                mx1 = fmaxf(mx1, fmaxf(s10, s11));
            }
            mx0 = fmaxf(mx0, __shfl_xor_sync(0xffffffffu, mx0, 1));
            mx0 = fmaxf(mx0, __shfl_xor_sync(0xffffffffu, mx0, 2));
            mx1 = fmaxf(mx1, __shfl_xor_sync(0xffffffffu, mx1, 1));
            mx1 = fmaxf(mx1, __shfl_xor_sync(0xffffffffu, mx1, 2));
            float mNew0 = fmaxf(mR0, mx0), mNew1 = fmaxf(mR1, mx1);
            float corr0 = __expf(mR0 - mNew0), corr1 = __expf(mR1 - mNew1);
            mR0 = mNew0; mR1 = mNew1;
            float rs0 = 0.f, rs1 = 0.f;
            float pv0[8][2], pv1[8][2];
#pragma unroll
            for (int f = 0; f < 8; f++) {
                pv0[f][0] = __expf(sv0[f][0] - mNew0);
                pv0[f][1] = __expf(sv0[f][1] - mNew0);
                pv1[f][0] = __expf(sv1[f][0] - mNew1);
                pv1[f][1] = __expf(sv1[f][1] - mNew1);
                rs0 += pv0[f][0] + pv0[f][1];
                rs1 += pv1[f][0] + pv1[f][1];
            }
            rs0 += __shfl_xor_sync(0xffffffffu, rs0, 1);
            rs0 += __shfl_xor_sync(0xffffffffu, rs0, 2);
            rs1 += __shfl_xor_sync(0xffffffffu, rs1, 1);
            rs1 += __shfl_xor_sync(0xffffffffu, rs1, 2);
            lR0 = lR0 * corr0 + rs0;
            lR1 = lR1 * corr1 + rs1;

            uint32_t ph[4][4], pl[4][4];
#pragma unroll
            for (int ks = 0; ks < 4; ks++) {
                split2h(pv0[2 * ks][0],     pv0[2 * ks][1],     ph[ks][0], pl[ks][0]);
                split2h(pv1[2 * ks][0],     pv1[2 * ks][1],     ph[ks][1], pl[ks][1]);
                split2h(pv0[2 * ks + 1][0], pv0[2 * ks + 1][1], ph[ks][2], pl[ks][2]);
                split2h(pv1[2 * ks + 1][0], pv1[2 * ks + 1][1], ph[ks][3], pl[ks][3]);
            }

            // GEMM3: O = O*corr + P*V
#pragma unroll
            for (int nd = 0; nd < 8; nd++) {
                o[nd][0] *= corr0; o[nd][1] *= corr0;
                o[nd][2] *= corr1; o[nd][3] *= corr1;
            }
#pragma unroll
            for (int ks = 0; ks < 4; ks++) {
                int k0 = ks * 16;
#pragma unroll
                for (int nd2 = 0; nd2 < 4; nd2++) {
                    uint32_t bh[4];
                    ldsBT(bh, tVh, nd2 * 16, k0, lane);
                    float* o0 = o[nd2 * 2 + 0];
                    float* o1 = o[nd2 * 2 + 1];
                    mma_f16(o0, ph[ks], bh); mma_f16(o1, ph[ks], bh + 2);
                    mma_f16(o0, pl[ks], bh); mma_f16(o1, pl[ks], bh + 2);
                }
            }
        }
    }

    // epilogue (hi only)
    {
        float inv0 = 1.f / lR0, inv1 = 1.f / lR1;
#pragma unroll
        for (int nd = 0; nd < 8; nd++) {
            int col = h * HD + nd * 8 + fc;
            size_t w = ((size_t)(i0 + il0) * V_DIM + col) >> 1;
            ((uint32_t*)g_ah)[w] = pack2h(o[nd][0] * inv0, o[nd][1] * inv0);
            w = ((size_t)(i0 + il1) * V_DIM + col) >> 1;
            ((uint32_t*)g_ah)[w] = pack2h(o[nd][2] * inv1, o[nd][3] * inv1);
        }
    }
}

// ---------------------------------------------------------------------------
extern "C" void kernel_launch(void* const* d_in, const int* in_sizes, int n_in,
                              void* d_out, int out_size)
{
    const float* x    = (const float*)d_in[0];
    const float* Wqkv = (const float*)d_in[1];
    const float* Wout = (const float*)d_in[2];
    const float* Wpos = (const float*)d_in[3];
    const float* u    = (const float*)d_in[4];
    const float* v    = (const float*)d_in[5];
    const float* rel  = (const float*)d_in[6];
    float* out = (float*)d_out;

    void *xh, *xl, *wqh, *rh, *rl, *wph, *ah, *woh;
    cudaGetSymbolAddress(&xh,  g_xh);  cudaGetSymbolAddress(&xl,  g_xl);
    cudaGetSymbolAddress(&wqh, g_wqh);
    cudaGetSymbolAddress(&rh,  g_rh);  cudaGetSymbolAddress(&rl,  g_rl);
    cudaGetSymbolAddress(&wph, g_wph);
    cudaGetSymbolAddress(&ah,  g_ah);
    cudaGetSymbolAddress(&woh, g_woh);

    cudaFuncSetAttribute(flash_xl_mma,
                         cudaFuncAttributeMaxDynamicSharedMemorySize, FL_SMEM);
    cudaFuncSetAttribute(gemm_proj,
                         cudaFuncAttributeMaxDynamicSharedMemorySize, GEMM_SMEM);
    cudaFuncSetAttribute(gemm_out,
                         cudaFuncAttributeMaxDynamicSharedMemorySize, OUT_SMEM);

    // 1) split all fp32 inputs
    split_all<<<9216, 256>>>((const float4*)x, (const float4*)Wqkv,
                             (const float4*)rel, (const float4*)Wpos,
                             (const float4*)Wout);

    // 2) merged qkv + pos projections (blocks 0-23: qkv; 24-31: pos)
    gemm_proj<<<dim3(32, 16), 512, GEMM_SMEM>>>(
        (const __half*)xh, (const __half*)xl, (const __half*)wqh,
        (const __half*)rh, (const __half*)rl, (const __half*)wph,
        u, v, V_DIM);

    // 3) fused attention -> g_ah (fp16, hi only); 64-row CTAs, 2/SM
    flash_xl_mma<<<dim3(NH, S_LEN / 64), 128, FL_SMEM>>>();

    // 4) out = attn @ Wout^T -> fp32 d_out  (A hi-only)
    gemm_out<<<dim3(V_DIM / 128, S_LEN / 128), 512, OUT_SMEM>>>(
        (const __half*)ah, (const __half*)woh, out, V_DIM, V_DIM);
}